// round 1
// baseline (speedup 1.0000x reference)
#include <cuda_runtime.h>
#include <cstdint>

#define LDIM   4800
#define CDIM   256
#define BATCH  2
#define TILE   128
#define KC     16
#define NTILE  38          // ceil(4800/128)
#define THRV   0.2f

// ---------------- deterministic scratch (static device globals; no allocs) ----
__device__ float               g_rowpart[BATCH * LDIM * NTILE];  // per-(l, s-tile) partial exp sums
__device__ float               g_colpart[BATCH * NTILE * LDIM];  // per-(l-tile, s) partial exp sums
__device__ float               g_invR[BATCH * LDIM];             // 1 / rowsum(exp)
__device__ float               g_invC[BATCH * LDIM];             // 1 / colsum(exp)
__device__ unsigned long long  g_rowmax[BATCH * LDIM];           // packed (conf_bits<<32)|(~argmax_s)
__device__ unsigned long long  g_colmax[BATCH * LDIM];           // packed (conf_bits<<32)|(~argmax_l)

__device__ __forceinline__ bool border_ok(int idx) {
    int h = idx / 80, w = idx % 80;                // 60x80 coarse grid, border 2
    return (h >= 2) && (h < 58) && (w >= 2) && (w < 78);
}

// ---------------- Pass 1: sim GEMM -> e = exp(sim), stored into conf buffer +
//                  deterministic per-tile row/col partial sums ------------------
__global__ __launch_bounds__(256, 2)
void k_gemm(const float* __restrict__ f0, const float* __restrict__ f1,
            const float* __restrict__ tempp, float* __restrict__ econf)
{
    __shared__ __align__(16) float As[KC][TILE];
    __shared__ __align__(16) float Bs[KC][TILE];

    const int b   = blockIdx.z;
    const int l0  = blockIdx.y * TILE;
    const int s0  = blockIdx.x * TILE;
    const int tid = threadIdx.x;
    const int tx  = tid & 15;
    const int ty  = tid >> 4;

    const float* A  = f0 + (size_t)b * LDIM * CDIM;
    const float* Bm = f1 + (size_t)b * LDIM * CDIM;

    // staging: each thread owns one tile row (sr) and 8 consecutive k
    const int sr   = tid >> 1;           // 0..127
    const int sk0  = (tid & 1) * 8;      // 0 or 8
    const int gl_s = l0 + sr;
    const int gs_s = s0 + sr;
    const bool aok = gl_s < LDIM;
    const bool bok = gs_s < LDIM;
    const float* Arow = A  + (size_t)(aok ? gl_s : 0) * CDIM + sk0;
    const float* Brow = Bm + (size_t)(bok ? gs_s : 0) * CDIM + sk0;
    const float4 z4 = make_float4(0.f, 0.f, 0.f, 0.f);

    float acc[8][8];
#pragma unroll
    for (int i = 0; i < 8; i++)
#pragma unroll
        for (int j = 0; j < 8; j++) acc[i][j] = 0.f;

    // prefetch chunk 0 into registers
    float4 sa0 = aok ? *(const float4*)(Arow)     : z4;
    float4 sa1 = aok ? *(const float4*)(Arow + 4) : z4;
    float4 sb0 = bok ? *(const float4*)(Brow)     : z4;
    float4 sb1 = bok ? *(const float4*)(Brow + 4) : z4;

    const int NKC = CDIM / KC;   // 16
    for (int kc = 0; kc < NKC; kc++) {
        __syncthreads();
        As[sk0 + 0][sr] = sa0.x; As[sk0 + 1][sr] = sa0.y;
        As[sk0 + 2][sr] = sa0.z; As[sk0 + 3][sr] = sa0.w;
        As[sk0 + 4][sr] = sa1.x; As[sk0 + 5][sr] = sa1.y;
        As[sk0 + 6][sr] = sa1.z; As[sk0 + 7][sr] = sa1.w;
        Bs[sk0 + 0][sr] = sb0.x; Bs[sk0 + 1][sr] = sb0.y;
        Bs[sk0 + 2][sr] = sb0.z; Bs[sk0 + 3][sr] = sb0.w;
        Bs[sk0 + 4][sr] = sb1.x; Bs[sk0 + 5][sr] = sb1.y;
        Bs[sk0 + 6][sr] = sb1.z; Bs[sk0 + 7][sr] = sb1.w;
        __syncthreads();

        if (kc + 1 < NKC) {     // prefetch next chunk; latency hides under FMAs
            const float* ap = Arow + (kc + 1) * KC;
            const float* bp = Brow + (kc + 1) * KC;
            sa0 = aok ? *(const float4*)(ap)     : z4;
            sa1 = aok ? *(const float4*)(ap + 4) : z4;
            sb0 = bok ? *(const float4*)(bp)     : z4;
            sb1 = bok ? *(const float4*)(bp + 4) : z4;
        }

#pragma unroll
        for (int k = 0; k < KC; k++) {
            float av[8], bv[8];
            *(float4*)&av[0] = *(const float4*)&As[k][ty * 8];
            *(float4*)&av[4] = *(const float4*)&As[k][ty * 8 + 4];
            *(float4*)&bv[0] = *(const float4*)&Bs[k][tx * 8];
            *(float4*)&bv[4] = *(const float4*)&Bs[k][tx * 8 + 4];
#pragma unroll
            for (int i = 0; i < 8; i++)
#pragma unroll
                for (int j = 0; j < 8; j++)
                    acc[i][j] = fmaf(av[i], bv[j], acc[i][j]);
        }
    }

    // ---- epilogue: e = exp(sim * temp / 256); store + partial sums ----
    const float scale = tempp[0] * (1.0f / 256.0f);   // temp * (1/sqrt(C))^2, exact pow2
    const int gl0 = l0 + ty * 8;
    const int gs0 = s0 + tx * 8;
    const bool rok = gl0 < LDIM;     // 4800 % 8 == 0 -> whole 8-group valid or not
    const bool cok = gs0 < LDIM;

    float rsum[8], csum[8];
#pragma unroll
    for (int i = 0; i < 8; i++) { rsum[i] = 0.f; csum[i] = 0.f; }

#pragma unroll
    for (int i = 0; i < 8; i++) {
        float ev[8];
#pragma unroll
        for (int j = 0; j < 8; j++) {
            float e = 0.f;
            if (rok && cok) e = __expf(acc[i][j] * scale);
            ev[j] = e;
            rsum[i] += e;
            csum[j] += e;
        }
        if (rok && cok) {
            size_t off = ((size_t)b * LDIM + (gl0 + i)) * LDIM + gs0;
            *(float4*)(econf + off)     = make_float4(ev[0], ev[1], ev[2], ev[3]);
            *(float4*)(econf + off + 4) = make_float4(ev[4], ev[5], ev[6], ev[7]);
        }
    }

    __syncthreads();
    float (*red)[TILE] = (float (*)[TILE])As;   // reuse smem: [16][128]

    // row partials: row r = ty*8+i, partial over this thread's 8 cols
#pragma unroll
    for (int i = 0; i < 8; i++) red[tx][ty * 8 + i] = rsum[i];
    __syncthreads();
    if (tid < TILE) {
        float s = 0.f;
#pragma unroll
        for (int x = 0; x < 16; x++) s += red[x][tid];   // fixed order: deterministic
        if (l0 + tid < LDIM)
            g_rowpart[((size_t)b * LDIM + l0 + tid) * NTILE + blockIdx.x] = s;
    }
    __syncthreads();
#pragma unroll
    for (int j = 0; j < 8; j++) red[ty][tx * 8 + j] = csum[j];
    __syncthreads();
    if (tid < TILE) {
        float s = 0.f;
#pragma unroll
        for (int y = 0; y < 16; y++) s += red[y][tid];
        if (s0 + tid < LDIM)
            g_colpart[((size_t)b * NTILE + blockIdx.y) * LDIM + s0 + tid] = s;
    }
}

// ---------------- Pass 1b: fixed-order reduction of partials; reset max keys --
__global__ void k_reduce()
{
    int t = blockIdx.x * blockDim.x + threadIdx.x;
    const int n = BATCH * LDIM;
    if (t < n) {
        float s = 0.f;
#pragma unroll
        for (int i = 0; i < NTILE; i++) s += g_rowpart[(size_t)t * NTILE + i];
        g_invR[t]   = 1.f / s;
        g_rowmax[t] = 0ull;
    } else if (t < 2 * n) {
        int u = t - n;
        int b = u / LDIM, sidx = u % LDIM;
        float s = 0.f;
#pragma unroll
        for (int i = 0; i < NTILE; i++) s += g_colpart[((size_t)b * NTILE + i) * LDIM + sidx];
        g_invC[u]   = 1.f / s;
        g_colmax[u] = 0ull;
    }
}

// ---------------- Pass 2: conf = e^2*invR*invC (in place), mconf = 0,
//                  row/col max+argmax via packed u64 atomicMax (deterministic) --
__global__ __launch_bounds__(256)
void k_conf(float* __restrict__ conf, float* __restrict__ mconf)
{
    const int b  = blockIdx.z;
    const int l0 = blockIdx.y * 128;
    const int s0 = blockIdx.x * 256;
    const int t  = threadIdx.x;
    const int j  = s0 + t;
    const bool jok = j < LDIM;
    const float invc = jok ? g_invC[b * LDIM + j] : 0.f;
    const unsigned int jkey = jok ? (0xFFFFFFFFu ^ (unsigned)j) : 0u;

    __shared__ unsigned long long wr[8][128];
    const int warp = t >> 5;
    unsigned long long cmax = 0ull;

    for (int r = 0; r < 128; r++) {
        const int l = l0 + r;
        float cf = 0.f;
        if (jok && l < LDIM) {
            size_t off = ((size_t)b * LDIM + l) * LDIM + j;
            float e = conf[off];
            cf = e * e * g_invR[b * LDIM + l] * invc;   // softmax_l * softmax_s
            conf[off]  = cf;
            mconf[off] = 0.f;
        }
        unsigned int bits = __float_as_uint(cf);        // cf >= 0 -> int order == float order
        unsigned long long ck = ((unsigned long long)bits << 32) | (0xFFFFFFFFu ^ (unsigned)l);
        cmax = (ck > cmax) ? ck : cmax;

        unsigned long long rk = ((unsigned long long)bits << 32) | jkey;
#pragma unroll
        for (int o = 16; o > 0; o >>= 1) {
            unsigned long long other = __shfl_down_sync(0xFFFFFFFFu, rk, o);
            rk = (other > rk) ? other : rk;
        }
        if ((t & 31) == 0) wr[warp][r] = rk;
    }

    if (jok) atomicMax(&g_colmax[b * LDIM + j], cmax);
    __syncthreads();
    if (t < 128) {
        unsigned long long m = 0ull;
#pragma unroll
        for (int w = 0; w < 8; w++) m = (wr[w][t] > m) ? wr[w][t] : m;
        int l = l0 + t;
        if (l < LDIM) atomicMax(&g_rowmax[b * LDIM + l], m);
    }
}

// ---------------- Pass 3: mutual-NN + threshold + border -> sparse mconf writes
__global__ void k_select(float* __restrict__ mconf)
{
    int t = blockIdx.x * blockDim.x + threadIdx.x;
    const int n = BATCH * LDIM;
    if (t >= 2 * n) return;
    const bool isrow = (t < n);
    const int  u = isrow ? t : (t - n);
    const int  b = u / LDIM;
    const int  p = u % LDIM;

    unsigned long long key = isrow ? g_rowmax[u] : g_colmax[u];
    float v = __uint_as_float((unsigned)(key >> 32));
    unsigned q = 0xFFFFFFFFu ^ (unsigned)key;
    if (!(v > THRV)) return;
    if (q >= (unsigned)LDIM) return;

    int l = isrow ? p : (int)q;
    int s = isrow ? (int)q : p;
    if (!border_ok(l) || !border_ok(s)) return;

    unsigned long long okey = isrow ? g_colmax[b * LDIM + s] : g_rowmax[b * LDIM + l];
    float ov = __uint_as_float((unsigned)(okey >> 32));
    if (ov == v)   // attains both row max and col max
        mconf[((size_t)b * LDIM + l) * LDIM + s] = v;
}

// ---------------- launch -------------------------------------------------------
extern "C" void kernel_launch(void* const* d_in, const int* in_sizes, int n_in,
                              void* d_out, int out_size)
{
    const float *f0 = nullptr, *f1 = nullptr, *temp = nullptr;
    for (int i = 0; i < n_in; i++) {
        if (in_sizes[i] == 1) { if (!temp) temp = (const float*)d_in[i]; }
        else { if (!f0) f0 = (const float*)d_in[i]; else if (!f1) f1 = (const float*)d_in[i]; }
    }

    float* conf  = (float*)d_out;
    float* mconf = conf + (size_t)out_size / 2;

    dim3 g1(NTILE, NTILE, BATCH);
    k_gemm<<<g1, 256>>>(f0, f1, temp, conf);

    const int n2 = 2 * BATCH * LDIM;
    k_reduce<<<(n2 + 255) / 256, 256>>>();

    dim3 g2((LDIM + 255) / 256, (LDIM + 127) / 128, BATCH);
    k_conf<<<g2, 256>>>(conf, mconf);

    k_select<<<(n2 + 255) / 256, 256>>>(mconf);
}

// round 3
// speedup vs baseline: 1.8691x; 1.8691x over previous
#include <cuda_runtime.h>
#include <cuda_bf16.h>
#include <cstdint>

#define LDIM   4800
#define CDIM   256
#define BATCH  2
#define BM     128
#define BN     128
#define BK     64
#define NT     38          // ceil(4800/128), both dims
#define THRV   0.2f

// ---------------- static device scratch (no allocations) ----------------------
__device__ __nv_bfloat16 g_h0[BATCH * LDIM * CDIM];
__device__ __nv_bfloat16 g_l0[BATCH * LDIM * CDIM];
__device__ __nv_bfloat16 g_h1[BATCH * LDIM * CDIM];
__device__ __nv_bfloat16 g_l1[BATCH * LDIM * CDIM];
__device__ float               g_rowpart[BATCH * LDIM * NT];
__device__ float               g_colpart[BATCH * NT * LDIM];
__device__ float               g_invR[BATCH * LDIM];
__device__ float               g_invC[BATCH * LDIM];
__device__ unsigned long long  g_rowmax[BATCH * LDIM];
__device__ unsigned long long  g_colmax[BATCH * LDIM];

// ---------------- helpers ------------------------------------------------------
static __device__ __forceinline__ uint32_t smem_u32(const void* p) {
    uint32_t a;
    asm("{ .reg .u64 t; cvta.to.shared.u64 t, %1; cvt.u32.u64 %0, t; }" : "=r"(a) : "l"(p));
    return a;
}
#define CP16(saddr, gptr) \
    asm volatile("cp.async.cg.shared.global [%0], [%1], 16;" :: "r"(saddr), "l"(gptr) : "memory")
#define CP_COMMIT() asm volatile("cp.async.commit_group;" ::: "memory")
#define CP_WAIT(n)  asm volatile("cp.async.wait_group %0;" :: "n"(n) : "memory")

static __device__ __forceinline__ void ldsm4(uint32_t* f, uint32_t addr) {
    asm volatile("ldmatrix.sync.aligned.m8n8.x4.shared.b16 {%0,%1,%2,%3}, [%4];"
                 : "=r"(f[0]), "=r"(f[1]), "=r"(f[2]), "=r"(f[3]) : "r"(addr));
}
static __device__ __forceinline__ void mma16816(float* d, const uint32_t* a,
                                                uint32_t b0, uint32_t b1) {
    asm volatile("mma.sync.aligned.m16n8k16.row.col.f32.bf16.bf16.f32 "
                 "{%0,%1,%2,%3}, {%4,%5,%6,%7}, {%8,%9}, {%0,%1,%2,%3};"
                 : "+f"(d[0]), "+f"(d[1]), "+f"(d[2]), "+f"(d[3])
                 : "r"(a[0]), "r"(a[1]), "r"(a[2]), "r"(a[3]), "r"(b0), "r"(b1));
}
// fast exp2: FFMA-only (no MUFU). |y| <= ~24 here. rel err ~2e-6.
static __device__ __forceinline__ float fexp2(float y) {
    float m = y + 12582912.f;              // round-to-nearest int via fp add
    float r = y - (m - 12582912.f);        // r in [-0.5, 0.5]
    float p =               1.3333558e-3f;
    p = fmaf(p, r,          9.6181291e-3f);
    p = fmaf(p, r,          5.5504109e-2f);
    p = fmaf(p, r,          2.4022651e-1f);
    p = fmaf(p, r,          6.9314718e-1f);
    p = fmaf(p, r,          1.0f);
    return __uint_as_float(__float_as_uint(p) + (__float_as_uint(m) << 23));
}
__device__ __forceinline__ bool border_ok(int idx) {
    int h = idx / 80, w = idx % 80;
    return (h >= 2) && (h < 58) && (w >= 2) && (w < 78);
}

// smem: A stages @0,@16384; B stages @32768,@49152. Epilogue scratch reuses @0.
#define SMEM_BYTES 65536

// ---------------- Pass 0: fp32 -> bf16 hi/lo split -----------------------------
__global__ void k_split(const float* __restrict__ f0, const float* __restrict__ f1) {
    const int NH = BATCH * LDIM * CDIM / 8;
    int t = blockIdx.x * blockDim.x + threadIdx.x;
    if (t >= 2 * NH) return;
    int half = (t >= NH);
    size_t off = (size_t)(half ? t - NH : t) * 8;
    const float4* s = (const float4*)((half ? f1 : f0) + off);
    float4 a = s[0], b = s[1];
    float x[8] = {a.x, a.y, a.z, a.w, b.x, b.y, b.z, b.w};
    uint32_t hw[4], lw[4];
#pragma unroll
    for (int i = 0; i < 4; i++) {
        __nv_bfloat162 h = __floats2bfloat162_rn(x[2 * i], x[2 * i + 1]);
        float r0 = x[2 * i]     - __bfloat162float(h.x);
        float r1 = x[2 * i + 1] - __bfloat162float(h.y);
        __nv_bfloat162 l = __floats2bfloat162_rn(r0, r1);
        hw[i] = *(uint32_t*)&h;
        lw[i] = *(uint32_t*)&l;
    }
    *(uint4*)((half ? g_h1 : g_h0) + off) = make_uint4(hw[0], hw[1], hw[2], hw[3]);
    *(uint4*)((half ? g_l1 : g_l0) + off) = make_uint4(lw[0], lw[1], lw[2], lw[3]);
}

// ---------------- Pass 1: HMMA GEMM (3-way bf16 split) + fexp2 epilogue --------
__global__ __launch_bounds__(256)
void k_gemm_hmma(const float* __restrict__ tempp, float* __restrict__ econf)
{
    extern __shared__ char smc[];
    const uint32_t sbase = smem_u32(smc);
    const uint32_t sA[2] = {sbase,         sbase + 16384};
    const uint32_t sB[2] = {sbase + 32768, sbase + 49152};

    const int b  = blockIdx.z;
    const int mt = blockIdx.y;
    const int nt = blockIdx.x;
    const int l0 = mt * BM;
    const int s0 = nt * BN;
    const int tid  = threadIdx.x;
    const int lane = tid & 31;
    const int wid  = tid >> 5;
    const int wm   = wid & 3;          // 4 warps in M (32 rows each)
    const int wn   = wid >> 2;         // 2 warps in N (64 cols each)
    const size_t bb = (size_t)b * LDIM * CDIM;

    const __nv_bfloat16* Apass[3] = {g_h0, g_h0, g_l0};
    const __nv_bfloat16* Bpass[3] = {g_h1, g_l1, g_h1};

    float acc[2][8][4];
#pragma unroll
    for (int i = 0; i < 2; i++)
#pragma unroll
        for (int j = 0; j < 8; j++)
#pragma unroll
            for (int q = 0; q < 4; q++) acc[i][j][q] = 0.f;

    auto issue = [&](int c) {
        const int pass = c >> 2, kc = c & 3, st = c & 1;
        const __nv_bfloat16* A = Apass[pass] + bb + kc * BK;
        const __nv_bfloat16* B = Bpass[pass] + bb + kc * BK;
#pragma unroll
        for (int i = 0; i < 4; i++) {
            int v = tid + 256 * i;
            int r = v >> 3, u = v & 7;
            uint32_t off = (uint32_t)(r * 128 + ((u ^ (r & 7)) << 4));
            int ga = l0 + r; if (ga >= LDIM) ga = 0;
            CP16(sA[st] + off, (const char*)(A + (size_t)ga * CDIM + u * 8));
            int gbr = s0 + r; if (gbr >= LDIM) gbr = 0;
            CP16(sB[st] + off, (const char*)(B + (size_t)gbr * CDIM + u * 8));
        }
    };

    issue(0);
    CP_COMMIT();

    for (int c = 0; c < 12; c++) {
        if (c < 11) { issue(c + 1); CP_COMMIT(); CP_WAIT(1); }
        else        { CP_WAIT(0); }
        __syncthreads();

        const int st = c & 1;
#pragma unroll
        for (int ks = 0; ks < 4; ks++) {
            uint32_t af[2][4], bf[4][4];
            const uint32_t cu = (uint32_t)((ks * 2 + (lane >> 4)) << 4);
#pragma unroll
            for (int mb = 0; mb < 2; mb++) {
                int row = wm * 32 + mb * 16 + (lane & 15);
                uint32_t off = (uint32_t)(row * 128) + (cu ^ (uint32_t)((row & 7) << 4));
                ldsm4(af[mb], sA[st] + off);
            }
#pragma unroll
            for (int ng = 0; ng < 4; ng++) {
                int row = wn * 64 + ng * 16 + (lane & 15);
                uint32_t off = (uint32_t)(row * 128) + (cu ^ (uint32_t)((row & 7) << 4));
                ldsm4(bf[ng], sB[st] + off);
            }
#pragma unroll
            for (int mb = 0; mb < 2; mb++)
#pragma unroll
                for (int nb = 0; nb < 8; nb++)
                    mma16816(acc[mb][nb], af[mb], bf[nb >> 1][nb & 1], bf[nb >> 1][(nb & 1) + 2]);
        }
        __syncthreads();
    }

    // ---- epilogue: e = 2^(sim * temp * log2e / 256); sums + coalesced stores --
    const float scale = tempp[0] * (1.4426950408889634f / 256.0f);
    const int rbase = l0 + wm * 32 + (lane >> 2);
    const int cbase = s0 + wn * 64 + 2 * (lane & 3);

    float rsum[4] = {0.f, 0.f, 0.f, 0.f};
    float csum0[8], csum1[8];
#pragma unroll
    for (int nb = 0; nb < 8; nb++) { csum0[nb] = 0.f; csum1[nb] = 0.f; }

#pragma unroll
    for (int mb = 0; mb < 2; mb++) {
        const int glA = rbase + mb * 16;
        const int glB = glA + 8;
        const bool vA = glA < LDIM, vB = glB < LDIM;
#pragma unroll
        for (int nb = 0; nb < 8; nb++) {
            const int gc = cbase + nb * 8;
            const bool vc = gc < LDIM;
            float e0 = fexp2(acc[mb][nb][0] * scale);
            float e1 = fexp2(acc[mb][nb][1] * scale);
            float e2 = fexp2(acc[mb][nb][2] * scale);
            float e3 = fexp2(acc[mb][nb][3] * scale);
            if (!(vA && vc)) { e0 = 0.f; e1 = 0.f; }
            if (!(vB && vc)) { e2 = 0.f; e3 = 0.f; }
            rsum[mb * 2 + 0] += e0 + e1;
            rsum[mb * 2 + 1] += e2 + e3;
            csum0[nb] += e0 + e2;
            csum1[nb] += e1 + e3;
            if (vA && vc) *(float2*)(econf + ((size_t)b * LDIM + glA) * LDIM + gc) = make_float2(e0, e1);
            if (vB && vc) *(float2*)(econf + ((size_t)b * LDIM + glB) * LDIM + gc) = make_float2(e2, e3);
        }
    }

    // quad-reduce row sums (lanes sharing lane>>2)
#pragma unroll
    for (int h = 0; h < 4; h++) {
        rsum[h] += __shfl_xor_sync(0xFFFFFFFFu, rsum[h], 1);
        rsum[h] += __shfl_xor_sync(0xFFFFFFFFu, rsum[h], 2);
    }
    // cross-quad reduce col sums (lanes sharing lane&3)
#pragma unroll
    for (int nb = 0; nb < 8; nb++) {
#pragma unroll
        for (int o = 4; o <= 16; o <<= 1) {
            csum0[nb] += __shfl_xor_sync(0xFFFFFFFFu, csum0[nb], o);
            csum1[nb] += __shfl_xor_sync(0xFFFFFFFFu, csum1[nb], o);
        }
    }

    float* rs = (float*)smc;            // [2][128]
    float* cs = (float*)(smc + 1024);   // [4][128]
    if ((lane & 3) == 0) {
#pragma unroll
        for (int h = 0; h < 4; h++) {
            int rl = wm * 32 + (h >> 1) * 16 + (h & 1) * 8 + (lane >> 2);
            rs[wn * 128 + rl] = rsum[h];
        }
    }
    if (lane < 4) {
#pragma unroll
        for (int nb = 0; nb < 8; nb++) {
            int cl = wn * 64 + nb * 8 + 2 * lane;
            cs[wm * 128 + cl]     = csum0[nb];
            cs[wm * 128 + cl + 1] = csum1[nb];
        }
    }
    __syncthreads();
    if (tid < 128) {
        float rv = rs[tid] + rs[128 + tid];
        if (l0 + tid < LDIM)
            g_rowpart[((size_t)b * LDIM + l0 + tid) * NT + nt] = rv;
        float cv = cs[tid] + cs[128 + tid] + cs[256 + tid] + cs[384 + tid];
        if (s0 + tid < LDIM)
            g_colpart[((size_t)b * NT + mt) * LDIM + s0 + tid] = cv;
    }
}

// ---------------- Pass 1b: fixed-order reduce; reset max keys ------------------
__global__ void k_reduce()
{
    int t = blockIdx.x * blockDim.x + threadIdx.x;
    const int n = BATCH * LDIM;
    if (t < n) {
        float s = 0.f;
#pragma unroll
        for (int i = 0; i < NT; i++) s += g_rowpart[(size_t)t * NT + i];
        g_invR[t]   = 1.f / s;
        g_rowmax[t] = 0ull;
    } else if (t < 2 * n) {
        int u = t - n;
        int b = u / LDIM, sidx = u % LDIM;
        float s = 0.f;
#pragma unroll
        for (int i = 0; i < NT; i++) s += g_colpart[((size_t)b * NT + i) * LDIM + sidx];
        g_invC[u]   = 1.f / s;
        g_colmax[u] = 0ull;
    }
}

// ---------------- Pass 2: conf = e^2*invR*invC; packed-u64 argmax --------------
__global__ __launch_bounds__(256)
void k_conf(float* __restrict__ conf, float* __restrict__ mconf)
{
    const int b  = blockIdx.z;
    const int l0 = blockIdx.y * 128;
    const int s0 = blockIdx.x * 256;
    const int t  = threadIdx.x;
    const int j  = s0 + t;
    const bool jok = j < LDIM;
    const float invc = jok ? g_invC[b * LDIM + j] : 0.f;
    const unsigned int jkey = jok ? (0xFFFFFFFFu ^ (unsigned)j) : 0u;

    __shared__ unsigned long long wr[8][128];
    const int warp = t >> 5;
    unsigned long long cmax = 0ull;

    for (int r = 0; r < 128; r++) {
        const int l = l0 + r;
        float cf = 0.f;
        if (jok && l < LDIM) {
            size_t off = ((size_t)b * LDIM + l) * LDIM + j;
            float e = conf[off];
            cf = e * e * g_invR[b * LDIM + l] * invc;
            conf[off]  = cf;
            mconf[off] = 0.f;
        }
        unsigned int bits = __float_as_uint(cf);
        unsigned long long ck = ((unsigned long long)bits << 32) | (0xFFFFFFFFu ^ (unsigned)l);
        cmax = (ck > cmax) ? ck : cmax;

        unsigned long long rk = ((unsigned long long)bits << 32) | jkey;
#pragma unroll
        for (int o = 16; o > 0; o >>= 1) {
            unsigned long long other = __shfl_down_sync(0xFFFFFFFFu, rk, o);
            rk = (other > rk) ? other : rk;
        }
        if ((t & 31) == 0) wr[warp][r] = rk;
    }

    if (jok) atomicMax(&g_colmax[b * LDIM + j], cmax);
    __syncthreads();
    if (t < 128) {
        unsigned long long m = 0ull;
#pragma unroll
        for (int w = 0; w < 8; w++) m = (wr[w][t] > m) ? wr[w][t] : m;
        int l = l0 + t;
        if (l < LDIM) atomicMax(&g_rowmax[b * LDIM + l], m);
    }
}

// ---------------- Pass 3: mutual-NN + threshold + border -----------------------
__global__ void k_select(float* __restrict__ mconf)
{
    int t = blockIdx.x * blockDim.x + threadIdx.x;
    const int n = BATCH * LDIM;
    if (t >= 2 * n) return;
    const bool isrow = (t < n);
    const int  u = isrow ? t : (t - n);
    const int  b = u / LDIM;
    const int  p = u % LDIM;

    unsigned long long key = isrow ? g_rowmax[u] : g_colmax[u];
    float v = __uint_as_float((unsigned)(key >> 32));
    unsigned q = 0xFFFFFFFFu ^ (unsigned)key;
    if (!(v > THRV)) return;
    if (q >= (unsigned)LDIM) return;

    int l = isrow ? p : (int)q;
    int s = isrow ? (int)q : p;
    if (!border_ok(l) || !border_ok(s)) return;

    unsigned long long okey = isrow ? g_colmax[b * LDIM + s] : g_rowmax[b * LDIM + l];
    float ov = __uint_as_float((unsigned)(okey >> 32));
    if (ov == v)
        mconf[((size_t)b * LDIM + l) * LDIM + s] = v;
}

// ---------------- launch -------------------------------------------------------
extern "C" void kernel_launch(void* const* d_in, const int* in_sizes, int n_in,
                              void* d_out, int out_size)
{
    const float *f0 = nullptr, *f1 = nullptr, *temp = nullptr;
    for (int i = 0; i < n_in; i++) {
        if (in_sizes[i] == 1) { if (!temp) temp = (const float*)d_in[i]; }
        else { if (!f0) f0 = (const float*)d_in[i]; else if (!f1) f1 = (const float*)d_in[i]; }
    }

    float* conf  = (float*)d_out;
    float* mconf = conf + (size_t)out_size / 2;

    cudaFuncSetAttribute(k_gemm_hmma, cudaFuncAttributeMaxDynamicSharedMemorySize, SMEM_BYTES);

    const int NSPLIT = 2 * BATCH * LDIM * CDIM / 8;
    k_split<<<(NSPLIT + 255) / 256, 256>>>(f0, f1);

    dim3 g1(NT, NT, BATCH);
    k_gemm_hmma<<<g1, 256, SMEM_BYTES>>>(temp, conf);

    const int n2 = 2 * BATCH * LDIM;
    k_reduce<<<(n2 + 255) / 256, 256>>>();

    dim3 g2((LDIM + 255) / 256, (LDIM + 127) / 128, BATCH);
    k_conf<<<g2, 256>>>(conf, mconf);

    k_select<<<(n2 + 255) / 256, 256>>>(mconf);
}

// round 4
// speedup vs baseline: 2.2581x; 1.2081x over previous
#include <cuda_runtime.h>
#include <cuda_bf16.h>
#include <cstdint>

#define LDIM   4800
#define CDIM   256
#define BATCH  2
#define BM     128
#define BN     128
#define BK     64
#define NT     38          // ceil(4800/128)
#define THRV   0.2f
#define CCOLS  1024        // k_conf cols per block (4 per thread)

// ---------------- static device scratch (no allocations) ----------------------
__device__ __nv_bfloat16 g_h0[BATCH * LDIM * CDIM];
__device__ __nv_bfloat16 g_l0[BATCH * LDIM * CDIM];
__device__ __nv_bfloat16 g_h1[BATCH * LDIM * CDIM];
__device__ __nv_bfloat16 g_l1[BATCH * LDIM * CDIM];
__device__ float               g_rowpart[BATCH * LDIM * NT];
__device__ float               g_colpart[BATCH * NT * LDIM];
__device__ float               g_invR[BATCH * LDIM];
__device__ float               g_invC[BATCH * LDIM];
__device__ unsigned long long  g_rowmax[BATCH * LDIM];
__device__ unsigned long long  g_colmax[BATCH * LDIM];

// ---------------- helpers ------------------------------------------------------
static __device__ __forceinline__ uint32_t smem_u32(const void* p) {
    uint32_t a;
    asm("{ .reg .u64 t; cvta.to.shared.u64 t, %1; cvt.u32.u64 %0, t; }" : "=r"(a) : "l"(p));
    return a;
}
#define CP16(saddr, gptr) \
    asm volatile("cp.async.cg.shared.global [%0], [%1], 16;" :: "r"(saddr), "l"(gptr) : "memory")
#define CP_COMMIT() asm volatile("cp.async.commit_group;" ::: "memory")
#define CP_WAIT(n)  asm volatile("cp.async.wait_group %0;" :: "n"(n) : "memory")

static __device__ __forceinline__ void ldsm4(uint32_t* f, uint32_t addr) {
    asm volatile("ldmatrix.sync.aligned.m8n8.x4.shared.b16 {%0,%1,%2,%3}, [%4];"
                 : "=r"(f[0]), "=r"(f[1]), "=r"(f[2]), "=r"(f[3]) : "r"(addr));
}
static __device__ __forceinline__ void mma16816(float* d, const uint32_t* a,
                                                uint32_t b0, uint32_t b1) {
    asm volatile("mma.sync.aligned.m16n8k16.row.col.f32.bf16.bf16.f32 "
                 "{%0,%1,%2,%3}, {%4,%5,%6,%7}, {%8,%9}, {%0,%1,%2,%3};"
                 : "+f"(d[0]), "+f"(d[1]), "+f"(d[2]), "+f"(d[3])
                 : "r"(a[0]), "r"(a[1]), "r"(a[2]), "r"(a[3]), "r"(b0), "r"(b1));
}
// fast exp2: FFMA-only. rel err ~2e-6.
static __device__ __forceinline__ float fexp2(float y) {
    float m = y + 12582912.f;
    float r = y - (m - 12582912.f);
    float p =               1.3333558e-3f;
    p = fmaf(p, r,          9.6181291e-3f);
    p = fmaf(p, r,          5.5504109e-2f);
    p = fmaf(p, r,          2.4022651e-1f);
    p = fmaf(p, r,          6.9314718e-1f);
    p = fmaf(p, r,          1.0f);
    return __uint_as_float(__float_as_uint(p) + (__float_as_uint(m) << 23));
}
__device__ __forceinline__ bool border_ok(int idx) {
    int h = idx / 80, w = idx % 80;
    return (h >= 2) && (h < 58) && (w >= 2) && (w < 78);
}

// smem: 3 stages x (A 16KB + B 16KB): A @ 0/16K/32K, B @ 48K/64K/80K.
#define SMEM_BYTES 98304

// ---------------- Pass 0: fp32 -> bf16 hi/lo split -----------------------------
__global__ void k_split(const float* __restrict__ f0, const float* __restrict__ f1) {
    const int NH = BATCH * LDIM * CDIM / 8;
    int t = blockIdx.x * blockDim.x + threadIdx.x;
    if (t >= 2 * NH) return;
    int half = (t >= NH);
    size_t off = (size_t)(half ? t - NH : t) * 8;
    const float4* s = (const float4*)((half ? f1 : f0) + off);
    float4 a = s[0], b = s[1];
    float x[8] = {a.x, a.y, a.z, a.w, b.x, b.y, b.z, b.w};
    uint32_t hw[4], lw[4];
#pragma unroll
    for (int i = 0; i < 4; i++) {
        __nv_bfloat162 h = __floats2bfloat162_rn(x[2 * i], x[2 * i + 1]);
        float r0 = x[2 * i]     - __bfloat162float(h.x);
        float r1 = x[2 * i + 1] - __bfloat162float(h.y);
        __nv_bfloat162 l = __floats2bfloat162_rn(r0, r1);
        hw[i] = *(uint32_t*)&h;
        lw[i] = *(uint32_t*)&l;
    }
    *(uint4*)((half ? g_h1 : g_h0) + off) = make_uint4(hw[0], hw[1], hw[2], hw[3]);
    *(uint4*)((half ? g_l1 : g_l0) + off) = make_uint4(lw[0], lw[1], lw[2], lw[3]);
}

// ---------------- Pass 1: HMMA GEMM (3-way bf16 split), 3-stage pipeline -------
__global__ __launch_bounds__(256)
void k_gemm_hmma(const float* __restrict__ tempp, float* __restrict__ econf)
{
    extern __shared__ char smc[];
    const uint32_t sbase = smem_u32(smc);
    const uint32_t sA[3] = {sbase,         sbase + 16384, sbase + 32768};
    const uint32_t sB[3] = {sbase + 49152, sbase + 65536, sbase + 81920};

    const int b  = blockIdx.z;
    const int mt = blockIdx.y;
    const int nt = blockIdx.x;
    const int l0 = mt * BM;
    const int s0 = nt * BN;
    const int tid  = threadIdx.x;
    const int lane = tid & 31;
    const int wid  = tid >> 5;
    const int wm   = wid & 3;
    const int wn   = wid >> 2;
    const size_t bb = (size_t)b * LDIM * CDIM;

    const __nv_bfloat16* Apass[3] = {g_h0, g_h0, g_l0};
    const __nv_bfloat16* Bpass[3] = {g_h1, g_l1, g_h1};

    float acc[2][8][4];
#pragma unroll
    for (int i = 0; i < 2; i++)
#pragma unroll
        for (int j = 0; j < 8; j++)
#pragma unroll
            for (int q = 0; q < 4; q++) acc[i][j][q] = 0.f;

    auto issue = [&](int c) {
        const int pass = c >> 2, kc = c & 3, st = c % 3;
        const __nv_bfloat16* A = Apass[pass] + bb + kc * BK;
        const __nv_bfloat16* B = Bpass[pass] + bb + kc * BK;
#pragma unroll
        for (int i = 0; i < 4; i++) {
            int v = tid + 256 * i;
            int r = v >> 3, u = v & 7;
            uint32_t off = (uint32_t)(r * 128 + ((u ^ (r & 7)) << 4));
            int ga = l0 + r; if (ga >= LDIM) ga = 0;
            CP16(sA[st] + off, (const char*)(A + (size_t)ga * CDIM + u * 8));
            int gbr = s0 + r; if (gbr >= LDIM) gbr = 0;
            CP16(sB[st] + off, (const char*)(B + (size_t)gbr * CDIM + u * 8));
        }
    };

    issue(0); CP_COMMIT();
    issue(1); CP_COMMIT();

    for (int c = 0; c < 12; c++) {
        if (c < 11) CP_WAIT(1); else CP_WAIT(0);
        __syncthreads();

        const int st = c % 3;
#pragma unroll
        for (int ks = 0; ks < 4; ks++) {
            uint32_t af[2][4], bf[4][4];
            const uint32_t cu = (uint32_t)((ks * 2 + (lane >> 4)) << 4);
#pragma unroll
            for (int mb = 0; mb < 2; mb++) {
                int row = wm * 32 + mb * 16 + (lane & 15);
                uint32_t off = (uint32_t)(row * 128) + (cu ^ (uint32_t)((row & 7) << 4));
                ldsm4(af[mb], sA[st] + off);
            }
#pragma unroll
            for (int ng = 0; ng < 4; ng++) {
                int row = wn * 64 + ng * 16 + (lane & 15);
                uint32_t off = (uint32_t)(row * 128) + (cu ^ (uint32_t)((row & 7) << 4));
                ldsm4(bf[ng], sB[st] + off);
            }
#pragma unroll
            for (int mb = 0; mb < 2; mb++)
#pragma unroll
                for (int nb = 0; nb < 8; nb++)
                    mma16816(acc[mb][nb], af[mb], bf[nb >> 1][nb & 1], bf[nb >> 1][(nb & 1) + 2]);
        }

        if (c < 10) { issue(c + 2); CP_COMMIT(); }   // overwrites stage (c-1)%3: safe, all
                                                     // warps passed this iter's barrier
    }
    __syncthreads();

    // ---- epilogue: e = 2^(sim * temp * log2e / 256); sums + coalesced stores --
    const float scale = tempp[0] * (1.4426950408889634f / 256.0f);
    const int rbase = l0 + wm * 32 + (lane >> 2);
    const int cbase = s0 + wn * 64 + 2 * (lane & 3);

    float rsum[4] = {0.f, 0.f, 0.f, 0.f};
    float csum0[8], csum1[8];
#pragma unroll
    for (int nb = 0; nb < 8; nb++) { csum0[nb] = 0.f; csum1[nb] = 0.f; }

#pragma unroll
    for (int mb = 0; mb < 2; mb++) {
        const int glA = rbase + mb * 16;
        const int glB = glA + 8;
        const bool vA = glA < LDIM, vB = glB < LDIM;
#pragma unroll
        for (int nb = 0; nb < 8; nb++) {
            const int gc = cbase + nb * 8;
            const bool vc = gc < LDIM;
            float e0 = fexp2(acc[mb][nb][0] * scale);
            float e1 = fexp2(acc[mb][nb][1] * scale);
            float e2 = fexp2(acc[mb][nb][2] * scale);
            float e3 = fexp2(acc[mb][nb][3] * scale);
            if (!(vA && vc)) { e0 = 0.f; e1 = 0.f; }
            if (!(vB && vc)) { e2 = 0.f; e3 = 0.f; }
            rsum[mb * 2 + 0] += e0 + e1;
            rsum[mb * 2 + 1] += e2 + e3;
            csum0[nb] += e0 + e2;
            csum1[nb] += e1 + e3;
            if (vA && vc) *(float2*)(econf + ((size_t)b * LDIM + glA) * LDIM + gc) = make_float2(e0, e1);
            if (vB && vc) *(float2*)(econf + ((size_t)b * LDIM + glB) * LDIM + gc) = make_float2(e2, e3);
        }
    }

#pragma unroll
    for (int h = 0; h < 4; h++) {
        rsum[h] += __shfl_xor_sync(0xFFFFFFFFu, rsum[h], 1);
        rsum[h] += __shfl_xor_sync(0xFFFFFFFFu, rsum[h], 2);
    }
#pragma unroll
    for (int nb = 0; nb < 8; nb++) {
#pragma unroll
        for (int o = 4; o <= 16; o <<= 1) {
            csum0[nb] += __shfl_xor_sync(0xFFFFFFFFu, csum0[nb], o);
            csum1[nb] += __shfl_xor_sync(0xFFFFFFFFu, csum1[nb], o);
        }
    }

    float* rs = (float*)smc;
    float* cs = (float*)(smc + 1024);
    if ((lane & 3) == 0) {
#pragma unroll
        for (int h = 0; h < 4; h++) {
            int rl = wm * 32 + (h >> 1) * 16 + (h & 1) * 8 + (lane >> 2);
            rs[wn * 128 + rl] = rsum[h];
        }
    }
    if (lane < 4) {
#pragma unroll
        for (int nb = 0; nb < 8; nb++) {
            int cl = wn * 64 + nb * 8 + 2 * lane;
            cs[wm * 128 + cl]     = csum0[nb];
            cs[wm * 128 + cl + 1] = csum1[nb];
        }
    }
    __syncthreads();
    if (tid < 128) {
        float rv = rs[tid] + rs[128 + tid];
        if (l0 + tid < LDIM)
            g_rowpart[((size_t)b * LDIM + l0 + tid) * NT + nt] = rv;
        float cv = cs[tid] + cs[128 + tid] + cs[256 + tid] + cs[384 + tid];
        if (s0 + tid < LDIM)
            g_colpart[((size_t)b * NT + mt) * LDIM + s0 + tid] = cv;
    }
}

// ---------------- Pass 1b: fixed-order reduce; reset max keys ------------------
__global__ void k_reduce()
{
    int t = blockIdx.x * blockDim.x + threadIdx.x;
    const int n = BATCH * LDIM;
    if (t < n) {
        float s = 0.f;
#pragma unroll
        for (int i = 0; i < NT; i++) s += g_rowpart[(size_t)t * NT + i];
        g_invR[t]   = 1.f / s;
        g_rowmax[t] = 0ull;
    } else if (t < 2 * n) {
        int u = t - n;
        int b = u / LDIM, sidx = u % LDIM;
        float s = 0.f;
#pragma unroll
        for (int i = 0; i < NT; i++) s += g_colpart[((size_t)b * NT + i) * LDIM + sidx];
        g_invC[u]   = 1.f / s;
        g_colmax[u] = 0ull;
    }
}

// ---------------- Pass 2 v2: float4, hoisted scales, cheap max tracking --------
__global__ __launch_bounds__(256)
void k_conf(float* __restrict__ conf, float* __restrict__ mconf)
{
    const int b  = blockIdx.z;
    const int l0 = blockIdx.y * 128;
    const int s0 = blockIdx.x * CCOLS;
    const int t  = threadIdx.x, warp = t >> 5, lane = t & 31;
    const int j0 = s0 + 4 * t;
    const bool jok = j0 < LDIM;            // 4800 % 4 == 0: all-or-nothing per thread

    __shared__ float sInvR[128];
    __shared__ unsigned long long wr[8][128];

    if (t < 128) {
        int l = l0 + t;
        sInvR[t] = (l < LDIM) ? g_invR[b * LDIM + l] : 0.f;
    }
    __syncthreads();

    const float4 invc = jok ? *(const float4*)(g_invC + b * LDIM + j0)
                            : make_float4(0.f, 0.f, 0.f, 0.f);

    float cv0 = -1.f, cv1 = -1.f, cv2 = -1.f, cv3 = -1.f;   // col max (value, row)
    int   ci0 = 0, ci1 = 0, ci2 = 0, ci3 = 0;

    const int rmax = (LDIM - l0 < 128) ? (LDIM - l0) : 128;
    size_t base = ((size_t)b * LDIM + l0) * LDIM + (jok ? j0 : 0);

    for (int r = 0; r < rmax; r++, base += LDIM) {
        unsigned long long rk = 0ull;
        if (jok) {
            float4 e = *(const float4*)(conf + base);
            const float tR = sInvR[r];
            float4 cf;
            cf.x = e.x * e.x * (tR * invc.x);
            cf.y = e.y * e.y * (tR * invc.y);
            cf.z = e.z * e.z * (tR * invc.z);
            cf.w = e.w * e.w * (tR * invc.w);
            *(float4*)(conf  + base) = cf;
            *(float4*)(mconf + base) = make_float4(0.f, 0.f, 0.f, 0.f);

            if (cf.x > cv0) { cv0 = cf.x; ci0 = r; }
            if (cf.y > cv1) { cv1 = cf.y; ci1 = r; }
            if (cf.z > cv2) { cv2 = cf.z; ci2 = r; }
            if (cf.w > cv3) { cv3 = cf.w; ci3 = r; }

            float a = cf.x; int ia = 0;
            if (cf.y > a) { a = cf.y; ia = 1; }
            if (cf.z > a) { a = cf.z; ia = 2; }
            if (cf.w > a) { a = cf.w; ia = 3; }
            rk = ((unsigned long long)__float_as_uint(a) << 32)
               | (0xFFFFFFFFu ^ (unsigned)(j0 + ia));
        }
#pragma unroll
        for (int o = 16; o > 0; o >>= 1) {
            unsigned long long oth = __shfl_down_sync(0xFFFFFFFFu, rk, o);
            rk = (oth > rk) ? oth : rk;
        }
        if (lane == 0) wr[warp][r] = rk;
    }

    if (jok) {
        atomicMax(&g_colmax[b * LDIM + j0 + 0],
                  ((unsigned long long)__float_as_uint(cv0) << 32) | (0xFFFFFFFFu ^ (unsigned)(l0 + ci0)));
        atomicMax(&g_colmax[b * LDIM + j0 + 1],
                  ((unsigned long long)__float_as_uint(cv1) << 32) | (0xFFFFFFFFu ^ (unsigned)(l0 + ci1)));
        atomicMax(&g_colmax[b * LDIM + j0 + 2],
                  ((unsigned long long)__float_as_uint(cv2) << 32) | (0xFFFFFFFFu ^ (unsigned)(l0 + ci2)));
        atomicMax(&g_colmax[b * LDIM + j0 + 3],
                  ((unsigned long long)__float_as_uint(cv3) << 32) | (0xFFFFFFFFu ^ (unsigned)(l0 + ci3)));
    }
    __syncthreads();
    if (t < rmax) {
        unsigned long long m = 0ull;
#pragma unroll
        for (int w = 0; w < 8; w++) m = (wr[w][t] > m) ? wr[w][t] : m;
        atomicMax(&g_rowmax[b * LDIM + l0 + t], m);
    }
}

// ---------------- Pass 3: mutual-NN + threshold + border -----------------------
__global__ void k_select(float* __restrict__ mconf)
{
    int t = blockIdx.x * blockDim.x + threadIdx.x;
    const int n = BATCH * LDIM;
    if (t >= 2 * n) return;
    const bool isrow = (t < n);
    const int  u = isrow ? t : (t - n);
    const int  b = u / LDIM;
    const int  p = u % LDIM;

    unsigned long long key = isrow ? g_rowmax[u] : g_colmax[u];
    float v = __uint_as_float((unsigned)(key >> 32));
    unsigned q = 0xFFFFFFFFu ^ (unsigned)key;
    if (!(v > THRV)) return;
    if (q >= (unsigned)LDIM) return;

    int l = isrow ? p : (int)q;
    int s = isrow ? (int)q : p;
    if (!border_ok(l) || !border_ok(s)) return;

    unsigned long long okey = isrow ? g_colmax[b * LDIM + s] : g_rowmax[b * LDIM + l];
    float ov = __uint_as_float((unsigned)(okey >> 32));
    if (ov == v)
        mconf[((size_t)b * LDIM + l) * LDIM + s] = v;
}

// ---------------- launch -------------------------------------------------------
extern "C" void kernel_launch(void* const* d_in, const int* in_sizes, int n_in,
                              void* d_out, int out_size)
{
    const float *f0 = nullptr, *f1 = nullptr, *temp = nullptr;
    for (int i = 0; i < n_in; i++) {
        if (in_sizes[i] == 1) { if (!temp) temp = (const float*)d_in[i]; }
        else { if (!f0) f0 = (const float*)d_in[i]; else if (!f1) f1 = (const float*)d_in[i]; }
    }

    float* conf  = (float*)d_out;
    float* mconf = conf + (size_t)out_size / 2;

    cudaFuncSetAttribute(k_gemm_hmma, cudaFuncAttributeMaxDynamicSharedMemorySize, SMEM_BYTES);

    const int NSPLIT = 2 * BATCH * LDIM * CDIM / 8;
    k_split<<<(NSPLIT + 255) / 256, 256>>>(f0, f1);

    dim3 g1(NT, NT, BATCH);
    k_gemm_hmma<<<g1, 256, SMEM_BYTES>>>(temp, conf);

    const int n2 = 2 * BATCH * LDIM;
    k_reduce<<<(n2 + 255) / 256, 256>>>();

    dim3 g2((LDIM + CCOLS - 1) / CCOLS, (LDIM + 127) / 128, BATCH);
    k_conf<<<g2, 256>>>(conf, mconf);

    k_select<<<(n2 + 255) / 256, 256>>>(mconf);
}

// round 5
// speedup vs baseline: 2.8068x; 1.2430x over previous
#include <cuda_runtime.h>
#include <cuda_fp16.h>
#include <cstdint>

#define LDIM   4800
#define CDIM   256
#define BATCH  2
#define BM     128
#define BN     128
#define BK     64
#define NT     38          // ceil(4800/128)
#define THRV   0.2f
#define CCOLS  1024        // k_conf cols per block (4 per thread)
#define CROWS  64          // k_conf rows per block

// ---------------- static device scratch (no allocations) ----------------------
__device__ __half g_h0[BATCH * LDIM * CDIM];
__device__ __half g_l0[BATCH * LDIM * CDIM];
__device__ __half g_h1[BATCH * LDIM * CDIM];
__device__ float               g_rowpart[BATCH * LDIM * NT];
__device__ float               g_colpart[BATCH * NT * LDIM];
__device__ float               g_invR[BATCH * LDIM];
__device__ float               g_invC[BATCH * LDIM];
__device__ unsigned long long  g_rowmax[BATCH * LDIM];
__device__ unsigned long long  g_colmax[BATCH * LDIM];

// ---------------- helpers ------------------------------------------------------
static __device__ __forceinline__ uint32_t smem_u32(const void* p) {
    uint32_t a;
    asm("{ .reg .u64 t; cvta.to.shared.u64 t, %1; cvt.u32.u64 %0, t; }" : "=r"(a) : "l"(p));
    return a;
}
#define CP16(saddr, gptr) \
    asm volatile("cp.async.cg.shared.global [%0], [%1], 16;" :: "r"(saddr), "l"(gptr) : "memory")
#define CP_COMMIT() asm volatile("cp.async.commit_group;" ::: "memory")
#define CP_WAIT(n)  asm volatile("cp.async.wait_group %0;" :: "n"(n) : "memory")

static __device__ __forceinline__ void ldsm4(uint32_t* f, uint32_t addr) {
    asm volatile("ldmatrix.sync.aligned.m8n8.x4.shared.b16 {%0,%1,%2,%3}, [%4];"
                 : "=r"(f[0]), "=r"(f[1]), "=r"(f[2]), "=r"(f[3]) : "r"(addr));
}
static __device__ __forceinline__ void mma16816(float* d, const uint32_t* a,
                                                uint32_t b0, uint32_t b1) {
    asm volatile("mma.sync.aligned.m16n8k16.row.col.f32.f16.f16.f32 "
                 "{%0,%1,%2,%3}, {%4,%5,%6,%7}, {%8,%9}, {%0,%1,%2,%3};"
                 : "+f"(d[0]), "+f"(d[1]), "+f"(d[2]), "+f"(d[3])
                 : "r"(a[0]), "r"(a[1]), "r"(a[2]), "r"(a[3]), "r"(b0), "r"(b1));
}
// fast exp2: FFMA-only. rel err ~2e-6.
static __device__ __forceinline__ float fexp2(float y) {
    float m = y + 12582912.f;
    float r = y - (m - 12582912.f);
    float p =               1.3333558e-3f;
    p = fmaf(p, r,          9.6181291e-3f);
    p = fmaf(p, r,          5.5504109e-2f);
    p = fmaf(p, r,          2.4022651e-1f);
    p = fmaf(p, r,          6.9314718e-1f);
    p = fmaf(p, r,          1.0f);
    return __uint_as_float(__float_as_uint(p) + (__float_as_uint(m) << 23));
}
__device__ __forceinline__ bool border_ok(int idx) {
    int h = idx / 80, w = idx % 80;
    return (h >= 2) && (h < 58) && (w >= 2) && (w < 78);
}

// smem: 3 stages x (A 16KB + B 16KB): A @ 0/16K/32K, B @ 48K/64K/80K.
#define SMEM_BYTES 98304

// ---------------- Pass 0: fp32 -> fp16 hi/lo split -----------------------------
__global__ void k_split(const float* __restrict__ f0, const float* __restrict__ f1) {
    const int NH = BATCH * LDIM * CDIM / 8;
    int t = blockIdx.x * blockDim.x + threadIdx.x;
    if (t >= 2 * NH) return;
    int half = (t >= NH);
    size_t off = (size_t)(half ? t - NH : t) * 8;
    const float4* s = (const float4*)((half ? f1 : f0) + off);
    float4 a = s[0], b = s[1];
    float x[8] = {a.x, a.y, a.z, a.w, b.x, b.y, b.z, b.w};
    uint32_t hw[4], lw[4];
#pragma unroll
    for (int i = 0; i < 4; i++) {
        __half2 h = __float22half2_rn(make_float2(x[2 * i], x[2 * i + 1]));
        float r0 = x[2 * i]     - __half2float(__low2half(h));
        float r1 = x[2 * i + 1] - __half2float(__high2half(h));
        __half2 l = __float22half2_rn(make_float2(r0, r1));
        hw[i] = *(uint32_t*)&h;
        lw[i] = *(uint32_t*)&l;
    }
    *(uint4*)((half ? g_h1 : g_h0) + off) = make_uint4(hw[0], hw[1], hw[2], hw[3]);
    if (!half)   // lo needed only for feat0 (we drop hi0*lo1)
        *(uint4*)(g_l0 + off) = make_uint4(lw[0], lw[1], lw[2], lw[3]);
}

// ---------------- Pass 1: HMMA GEMM (fp16 2-pass: h0*h1 + l0*h1) ---------------
__global__ __launch_bounds__(256)
void k_gemm_hmma(const float* __restrict__ tempp, float* __restrict__ econf,
                 float* __restrict__ mconf)
{
    extern __shared__ char smc[];
    const uint32_t sbase = smem_u32(smc);
    const uint32_t sA[3] = {sbase,         sbase + 16384, sbase + 32768};
    const uint32_t sB[3] = {sbase + 49152, sbase + 65536, sbase + 81920};

    const int b  = blockIdx.z;
    const int mt = blockIdx.y;
    const int nt = blockIdx.x;
    const int l0 = mt * BM;
    const int s0 = nt * BN;
    const int tid  = threadIdx.x;
    const int lane = tid & 31;
    const int wid  = tid >> 5;
    const int wm   = wid & 3;
    const int wn   = wid >> 2;
    const size_t bb = (size_t)b * LDIM * CDIM;

    const __half* Apass[2] = {g_h0, g_l0};
    const __half* Bpass[2] = {g_h1, g_h1};

    float acc[2][8][4];
#pragma unroll
    for (int i = 0; i < 2; i++)
#pragma unroll
        for (int j = 0; j < 8; j++)
#pragma unroll
            for (int q = 0; q < 4; q++) acc[i][j][q] = 0.f;

    auto issue = [&](int c) {
        const int pass = c >> 2, kc = c & 3, st = c % 3;
        const __half* A = Apass[pass] + bb + kc * BK;
        const __half* B = Bpass[pass] + bb + kc * BK;
#pragma unroll
        for (int i = 0; i < 4; i++) {
            int v = tid + 256 * i;
            int r = v >> 3, u = v & 7;
            uint32_t off = (uint32_t)(r * 128 + ((u ^ (r & 7)) << 4));
            int ga = l0 + r; if (ga >= LDIM) ga = 0;
            CP16(sA[st] + off, (const char*)(A + (size_t)ga * CDIM + u * 8));
            int gbr = s0 + r; if (gbr >= LDIM) gbr = 0;
            CP16(sB[st] + off, (const char*)(B + (size_t)gbr * CDIM + u * 8));
        }
    };

    issue(0); CP_COMMIT();
    issue(1); CP_COMMIT();

    for (int c = 0; c < 8; c++) {
        if (c < 7) CP_WAIT(1); else CP_WAIT(0);
        __syncthreads();

        const int st = c % 3;
#pragma unroll
        for (int ks = 0; ks < 4; ks++) {
            uint32_t af[2][4], bf[4][4];
            const uint32_t cu = (uint32_t)((ks * 2 + (lane >> 4)) << 4);
#pragma unroll
            for (int mb = 0; mb < 2; mb++) {
                int row = wm * 32 + mb * 16 + (lane & 15);
                uint32_t off = (uint32_t)(row * 128) + (cu ^ (uint32_t)((row & 7) << 4));
                ldsm4(af[mb], sA[st] + off);
            }
#pragma unroll
            for (int ng = 0; ng < 4; ng++) {
                int row = wn * 64 + ng * 16 + (lane & 15);
                uint32_t off = (uint32_t)(row * 128) + (cu ^ (uint32_t)((row & 7) << 4));
                ldsm4(bf[ng], sB[st] + off);
            }
#pragma unroll
            for (int mb = 0; mb < 2; mb++)
#pragma unroll
                for (int nb = 0; nb < 8; nb++)
                    mma16816(acc[mb][nb], af[mb], bf[nb >> 1][nb & 1], bf[nb >> 1][(nb & 1) + 2]);
        }

        if (c < 6) { issue(c + 2); CP_COMMIT(); }
    }
    __syncthreads();

    // ---- epilogue: e = 2^(sim*scale); sums, coalesced e stores, mconf zeros ---
    const float scale = tempp[0] * (1.4426950408889634f / 256.0f);
    const int rbase = l0 + wm * 32 + (lane >> 2);
    const int cbase = s0 + wn * 64 + 2 * (lane & 3);

    float rsum[4] = {0.f, 0.f, 0.f, 0.f};
    float csum0[8], csum1[8];
#pragma unroll
    for (int nb = 0; nb < 8; nb++) { csum0[nb] = 0.f; csum1[nb] = 0.f; }

#pragma unroll
    for (int mb = 0; mb < 2; mb++) {
        const int glA = rbase + mb * 16;
        const int glB = glA + 8;
        const bool vA = glA < LDIM, vB = glB < LDIM;
#pragma unroll
        for (int nb = 0; nb < 8; nb++) {
            const int gc = cbase + nb * 8;
            const bool vc = gc < LDIM;
            float e0 = fexp2(acc[mb][nb][0] * scale);
            float e1 = fexp2(acc[mb][nb][1] * scale);
            float e2 = fexp2(acc[mb][nb][2] * scale);
            float e3 = fexp2(acc[mb][nb][3] * scale);
            if (!(vA && vc)) { e0 = 0.f; e1 = 0.f; }
            if (!(vB && vc)) { e2 = 0.f; e3 = 0.f; }
            rsum[mb * 2 + 0] += e0 + e1;
            rsum[mb * 2 + 1] += e2 + e3;
            csum0[nb] += e0 + e2;
            csum1[nb] += e1 + e3;
            if (vA && vc) {
                size_t off = ((size_t)b * LDIM + glA) * LDIM + gc;
                *(float2*)(econf + off) = make_float2(e0, e1);
                *(float2*)(mconf + off) = make_float2(0.f, 0.f);
            }
            if (vB && vc) {
                size_t off = ((size_t)b * LDIM + glB) * LDIM + gc;
                *(float2*)(econf + off) = make_float2(e2, e3);
                *(float2*)(mconf + off) = make_float2(0.f, 0.f);
            }
        }
    }

#pragma unroll
    for (int h = 0; h < 4; h++) {
        rsum[h] += __shfl_xor_sync(0xFFFFFFFFu, rsum[h], 1);
        rsum[h] += __shfl_xor_sync(0xFFFFFFFFu, rsum[h], 2);
    }
#pragma unroll
    for (int nb = 0; nb < 8; nb++) {
#pragma unroll
        for (int o = 4; o <= 16; o <<= 1) {
            csum0[nb] += __shfl_xor_sync(0xFFFFFFFFu, csum0[nb], o);
            csum1[nb] += __shfl_xor_sync(0xFFFFFFFFu, csum1[nb], o);
        }
    }

    float* rs = (float*)smc;
    float* cs = (float*)(smc + 1024);
    if ((lane & 3) == 0) {
#pragma unroll
        for (int h = 0; h < 4; h++) {
            int rl = wm * 32 + (h >> 1) * 16 + (h & 1) * 8 + (lane >> 2);
            rs[wn * 128 + rl] = rsum[h];
        }
    }
    if (lane < 4) {
#pragma unroll
        for (int nb = 0; nb < 8; nb++) {
            int cl = wn * 64 + nb * 8 + 2 * lane;
            cs[wm * 128 + cl]     = csum0[nb];
            cs[wm * 128 + cl + 1] = csum1[nb];
        }
    }
    __syncthreads();
    if (tid < 128) {
        float rv = rs[tid] + rs[128 + tid];
        if (l0 + tid < LDIM)
            g_rowpart[((size_t)b * LDIM + l0 + tid) * NT + nt] = rv;
        float cv = cs[tid] + cs[128 + tid] + cs[256 + tid] + cs[384 + tid];
        if (s0 + tid < LDIM)
            g_colpart[((size_t)b * NT + mt) * LDIM + s0 + tid] = cv;
    }
}

// ---------------- Pass 1b: fixed-order reduce; reset max keys ------------------
__global__ void k_reduce()
{
    int t = blockIdx.x * blockDim.x + threadIdx.x;
    const int n = BATCH * LDIM;
    if (t < n) {
        float s = 0.f;
#pragma unroll
        for (int i = 0; i < NT; i++) s += g_rowpart[(size_t)t * NT + i];
        g_invR[t]   = 1.f / s;
        g_rowmax[t] = 0ull;
    } else if (t < 2 * n) {
        int u = t - n;
        int b = u / LDIM, sidx = u % LDIM;
        float s = 0.f;
#pragma unroll
        for (int i = 0; i < NT; i++) s += g_colpart[((size_t)b * NT + i) * LDIM + sidx];
        g_invC[u]   = 1.f / s;
        g_colmax[u] = 0ull;
    }
}

// ---------------- Pass 2: conf = e^2*invR*invC; 64 rows/block ------------------
__global__ __launch_bounds__(256)
void k_conf(float* __restrict__ conf)
{
    const int b  = blockIdx.z;
    const int l0 = blockIdx.y * CROWS;
    const int s0 = blockIdx.x * CCOLS;
    const int t  = threadIdx.x, warp = t >> 5, lane = t & 31;
    const int j0 = s0 + 4 * t;
    const bool jok = j0 < LDIM;

    __shared__ float sInvR[CROWS];
    __shared__ unsigned long long wr[8][CROWS];

    if (t < CROWS) sInvR[t] = g_invR[b * LDIM + l0 + t];
    __syncthreads();

    const float4 invc = jok ? *(const float4*)(g_invC + b * LDIM + j0)
                            : make_float4(0.f, 0.f, 0.f, 0.f);

    float cv0 = -1.f, cv1 = -1.f, cv2 = -1.f, cv3 = -1.f;
    int   ci0 = 0, ci1 = 0, ci2 = 0, ci3 = 0;

    size_t base = ((size_t)b * LDIM + l0) * LDIM + (jok ? j0 : 0);

    for (int r = 0; r < CROWS; r++, base += LDIM) {
        unsigned long long rk = 0ull;
        if (jok) {
            float4 e = *(const float4*)(conf + base);
            const float tR = sInvR[r];
            float4 cf;
            cf.x = e.x * e.x * (tR * invc.x);
            cf.y = e.y * e.y * (tR * invc.y);
            cf.z = e.z * e.z * (tR * invc.z);
            cf.w = e.w * e.w * (tR * invc.w);
            *(float4*)(conf + base) = cf;

            if (cf.x > cv0) { cv0 = cf.x; ci0 = r; }
            if (cf.y > cv1) { cv1 = cf.y; ci1 = r; }
            if (cf.z > cv2) { cv2 = cf.z; ci2 = r; }
            if (cf.w > cv3) { cv3 = cf.w; ci3 = r; }

            float a = cf.x; int ia = 0;
            if (cf.y > a) { a = cf.y; ia = 1; }
            if (cf.z > a) { a = cf.z; ia = 2; }
            if (cf.w > a) { a = cf.w; ia = 3; }
            rk = ((unsigned long long)__float_as_uint(a) << 32)
               | (0xFFFFFFFFu ^ (unsigned)(j0 + ia));
        }
#pragma unroll
        for (int o = 16; o > 0; o >>= 1) {
            unsigned long long oth = __shfl_down_sync(0xFFFFFFFFu, rk, o);
            rk = (oth > rk) ? oth : rk;
        }
        if (lane == 0) wr[warp][r] = rk;
    }

    if (jok) {
        atomicMax(&g_colmax[b * LDIM + j0 + 0],
                  ((unsigned long long)__float_as_uint(cv0) << 32) | (0xFFFFFFFFu ^ (unsigned)(l0 + ci0)));
        atomicMax(&g_colmax[b * LDIM + j0 + 1],
                  ((unsigned long long)__float_as_uint(cv1) << 32) | (0xFFFFFFFFu ^ (unsigned)(l0 + ci1)));
        atomicMax(&g_colmax[b * LDIM + j0 + 2],
                  ((unsigned long long)__float_as_uint(cv2) << 32) | (0xFFFFFFFFu ^ (unsigned)(l0 + ci2)));
        atomicMax(&g_colmax[b * LDIM + j0 + 3],
                  ((unsigned long long)__float_as_uint(cv3) << 32) | (0xFFFFFFFFu ^ (unsigned)(l0 + ci3)));
    }
    __syncthreads();
    if (t < CROWS) {
        unsigned long long m = 0ull;
#pragma unroll
        for (int w = 0; w < 8; w++) m = (wr[w][t] > m) ? wr[w][t] : m;
        atomicMax(&g_rowmax[b * LDIM + l0 + t], m);
    }
}

// ---------------- Pass 3: mutual-NN + threshold + border -----------------------
__global__ void k_select(float* __restrict__ mconf)
{
    int t = blockIdx.x * blockDim.x + threadIdx.x;
    const int n = BATCH * LDIM;
    if (t >= 2 * n) return;
    const bool isrow = (t < n);
    const int  u = isrow ? t : (t - n);
    const int  b = u / LDIM;
    const int  p = u % LDIM;

    unsigned long long key = isrow ? g_rowmax[u] : g_colmax[u];
    float v = __uint_as_float((unsigned)(key >> 32));
    unsigned q = 0xFFFFFFFFu ^ (unsigned)key;
    if (!(v > THRV)) return;
    if (q >= (unsigned)LDIM) return;

    int l = isrow ? p : (int)q;
    int s = isrow ? (int)q : p;
    if (!border_ok(l) || !border_ok(s)) return;

    unsigned long long okey = isrow ? g_colmax[b * LDIM + s] : g_rowmax[b * LDIM + l];
    float ov = __uint_as_float((unsigned)(okey >> 32));
    if (ov == v)
        mconf[((size_t)b * LDIM + l) * LDIM + s] = v;
}

// ---------------- launch -------------------------------------------------------
extern "C" void kernel_launch(void* const* d_in, const int* in_sizes, int n_in,
                              void* d_out, int out_size)
{
    const float *f0 = nullptr, *f1 = nullptr, *temp = nullptr;
    for (int i = 0; i < n_in; i++) {
        if (in_sizes[i] == 1) { if (!temp) temp = (const float*)d_in[i]; }
        else { if (!f0) f0 = (const float*)d_in[i]; else if (!f1) f1 = (const float*)d_in[i]; }
    }

    float* conf  = (float*)d_out;
    float* mconf = conf + (size_t)out_size / 2;

    cudaFuncSetAttribute(k_gemm_hmma, cudaFuncAttributeMaxDynamicSharedMemorySize, SMEM_BYTES);

    const int NSPLIT = 2 * BATCH * LDIM * CDIM / 8;
    k_split<<<(NSPLIT + 255) / 256, 256>>>(f0, f1);

    dim3 g1(NT, NT, BATCH);
    k_gemm_hmma<<<g1, 256, SMEM_BYTES>>>(temp, conf, mconf);

    const int n2 = 2 * BATCH * LDIM;
    k_reduce<<<(n2 + 255) / 256, 256>>>();

    dim3 g2((LDIM + CCOLS - 1) / CCOLS, LDIM / CROWS, BATCH);
    k_conf<<<g2, 256>>>(conf);

    k_select<<<(n2 + 255) / 256, 256>>>(mconf);
}

// round 6
// speedup vs baseline: 3.4569x; 1.2317x over previous
#include <cuda_runtime.h>
#include <cuda_fp16.h>
#include <cstdint>

#define LDIM   4800
#define CDIM   256
#define BATCH  2
#define BM     128
#define BN     128
#define BK     64
#define NT     38          // ceil(4800/128)
#define THRV   0.2f
#define CCOLS  1024        // k_conf cols per block (4 per thread)
#define CROWS  64          // k_conf rows per block

// ---------------- static device scratch (no allocations) ----------------------
__device__ __half g_h0[BATCH * LDIM * CDIM];
__device__ __half g_h1[BATCH * LDIM * CDIM];
__device__ float               g_rowpart[BATCH * LDIM * NT];
__device__ float               g_colpart[BATCH * NT * LDIM];
__device__ float               g_invR[BATCH * LDIM];
__device__ float               g_invC[BATCH * LDIM];
__device__ unsigned long long  g_rowmax[BATCH * LDIM];
__device__ unsigned long long  g_colmax[BATCH * LDIM];

// ---------------- helpers ------------------------------------------------------
static __device__ __forceinline__ uint32_t smem_u32(const void* p) {
    uint32_t a;
    asm("{ .reg .u64 t; cvta.to.shared.u64 t, %1; cvt.u32.u64 %0, t; }" : "=r"(a) : "l"(p));
    return a;
}
#define CP16(saddr, gptr) \
    asm volatile("cp.async.cg.shared.global [%0], [%1], 16;" :: "r"(saddr), "l"(gptr) : "memory")
#define CP_COMMIT() asm volatile("cp.async.commit_group;" ::: "memory")
#define CP_WAIT(n)  asm volatile("cp.async.wait_group %0;" :: "n"(n) : "memory")

static __device__ __forceinline__ void ldsm4(uint32_t* f, uint32_t addr) {
    asm volatile("ldmatrix.sync.aligned.m8n8.x4.shared.b16 {%0,%1,%2,%3}, [%4];"
                 : "=r"(f[0]), "=r"(f[1]), "=r"(f[2]), "=r"(f[3]) : "r"(addr));
}
static __device__ __forceinline__ void mma16816(float* d, const uint32_t* a,
                                                uint32_t b0, uint32_t b1) {
    asm volatile("mma.sync.aligned.m16n8k16.row.col.f32.f16.f16.f32 "
                 "{%0,%1,%2,%3}, {%4,%5,%6,%7}, {%8,%9}, {%0,%1,%2,%3};"
                 : "+f"(d[0]), "+f"(d[1]), "+f"(d[2]), "+f"(d[3])
                 : "r"(a[0]), "r"(a[1]), "r"(a[2]), "r"(a[3]), "r"(b0), "r"(b1));
}
// fast exp2: FFMA-only. rel err ~2e-6.
static __device__ __forceinline__ float fexp2(float y) {
    float m = y + 12582912.f;
    float r = y - (m - 12582912.f);
    float p =               1.3333558e-3f;
    p = fmaf(p, r,          9.6181291e-3f);
    p = fmaf(p, r,          5.5504109e-2f);
    p = fmaf(p, r,          2.4022651e-1f);
    p = fmaf(p, r,          6.9314718e-1f);
    p = fmaf(p, r,          1.0f);
    return __uint_as_float(__float_as_uint(p) + (__float_as_uint(m) << 23));
}
__device__ __forceinline__ bool border_ok(int idx) {
    int h = idx / 80, w = idx % 80;
    return (h >= 2) && (h < 58) && (w >= 2) && (w < 78);
}

// smem: 3 stages x (A 16KB + B 16KB): A @ 0/16K/32K, B @ 48K/64K/80K.
#define SMEM_BYTES 98304

// ---------------- Pass 0: fp32 -> fp16 (hi only, single-pass GEMM) -------------
__global__ void k_split(const float* __restrict__ f0, const float* __restrict__ f1) {
    const int NH = BATCH * LDIM * CDIM / 8;
    int t = blockIdx.x * blockDim.x + threadIdx.x;
    if (t >= 2 * NH) return;
    int half = (t >= NH);
    size_t off = (size_t)(half ? t - NH : t) * 8;
    const float4* s = (const float4*)((half ? f1 : f0) + off);
    float4 a = s[0], b = s[1];
    float x[8] = {a.x, a.y, a.z, a.w, b.x, b.y, b.z, b.w};
    uint32_t hw[4];
#pragma unroll
    for (int i = 0; i < 4; i++) {
        __half2 h = __float22half2_rn(make_float2(x[2 * i], x[2 * i + 1]));
        hw[i] = *(uint32_t*)&h;
    }
    *(uint4*)((half ? g_h1 : g_h0) + off) = make_uint4(hw[0], hw[1], hw[2], hw[3]);
}

// ---------------- Pass 1: HMMA GEMM (fp16 single pass) + fexp2 epilogue --------
__global__ __launch_bounds__(256)
void k_gemm_hmma(const float* __restrict__ tempp, float* __restrict__ econf,
                 float* __restrict__ mconf)
{
    extern __shared__ char smc[];
    const uint32_t sbase = smem_u32(smc);
    const uint32_t sA[3] = {sbase,         sbase + 16384, sbase + 32768};
    const uint32_t sB[3] = {sbase + 49152, sbase + 65536, sbase + 81920};

    const int b  = blockIdx.z;
    const int mt = blockIdx.y;
    const int nt = blockIdx.x;
    const int l0 = mt * BM;
    const int s0 = nt * BN;
    const int tid  = threadIdx.x;
    const int lane = tid & 31;
    const int wid  = tid >> 5;
    const int wm   = wid & 3;
    const int wn   = wid >> 2;
    const size_t bb = (size_t)b * LDIM * CDIM;

    float acc[2][8][4];
#pragma unroll
    for (int i = 0; i < 2; i++)
#pragma unroll
        for (int j = 0; j < 8; j++)
#pragma unroll
            for (int q = 0; q < 4; q++) acc[i][j][q] = 0.f;

    auto issue = [&](int c) {
        const int st = c % 3;
        const __half* A = g_h0 + bb + c * BK;
        const __half* B = g_h1 + bb + c * BK;
#pragma unroll
        for (int i = 0; i < 4; i++) {
            int v = tid + 256 * i;
            int r = v >> 3, u = v & 7;
            uint32_t off = (uint32_t)(r * 128 + ((u ^ (r & 7)) << 4));
            int ga = l0 + r; if (ga >= LDIM) ga = 0;
            CP16(sA[st] + off, (const char*)(A + (size_t)ga * CDIM + u * 8));
            int gbr = s0 + r; if (gbr >= LDIM) gbr = 0;
            CP16(sB[st] + off, (const char*)(B + (size_t)gbr * CDIM + u * 8));
        }
    };

    issue(0); CP_COMMIT();
    issue(1); CP_COMMIT();

    for (int c = 0; c < 4; c++) {
        if (c < 3) CP_WAIT(1); else CP_WAIT(0);
        __syncthreads();

        const int st = c % 3;
#pragma unroll
        for (int ks = 0; ks < 4; ks++) {
            uint32_t af[2][4], bf[4][4];
            const uint32_t cu = (uint32_t)((ks * 2 + (lane >> 4)) << 4);
#pragma unroll
            for (int mb = 0; mb < 2; mb++) {
                int row = wm * 32 + mb * 16 + (lane & 15);
                uint32_t off = (uint32_t)(row * 128) + (cu ^ (uint32_t)((row & 7) << 4));
                ldsm4(af[mb], sA[st] + off);
            }
#pragma unroll
            for (int ng = 0; ng < 4; ng++) {
                int row = wn * 64 + ng * 16 + (lane & 15);
                uint32_t off = (uint32_t)(row * 128) + (cu ^ (uint32_t)((row & 7) << 4));
                ldsm4(bf[ng], sB[st] + off);
            }
#pragma unroll
            for (int mb = 0; mb < 2; mb++)
#pragma unroll
                for (int nb = 0; nb < 8; nb++)
                    mma16816(acc[mb][nb], af[mb], bf[nb >> 1][nb & 1], bf[nb >> 1][(nb & 1) + 2]);
        }

        if (c < 2) { issue(c + 2); CP_COMMIT(); }
    }
    __syncthreads();

    // ---- epilogue: e = 2^(sim*scale); sums, coalesced e stores, mconf zeros ---
    const float scale = tempp[0] * (1.4426950408889634f / 256.0f);
    const int rbase = l0 + wm * 32 + (lane >> 2);
    const int cbase = s0 + wn * 64 + 2 * (lane & 3);

    float rsum[4] = {0.f, 0.f, 0.f, 0.f};
    float csum0[8], csum1[8];
#pragma unroll
    for (int nb = 0; nb < 8; nb++) { csum0[nb] = 0.f; csum1[nb] = 0.f; }

#pragma unroll
    for (int mb = 0; mb < 2; mb++) {
        const int glA = rbase + mb * 16;
        const int glB = glA + 8;
        const bool vA = glA < LDIM, vB = glB < LDIM;
#pragma unroll
        for (int nb = 0; nb < 8; nb++) {
            const int gc = cbase + nb * 8;
            const bool vc = gc < LDIM;
            float e0 = fexp2(acc[mb][nb][0] * scale);
            float e1 = fexp2(acc[mb][nb][1] * scale);
            float e2 = fexp2(acc[mb][nb][2] * scale);
            float e3 = fexp2(acc[mb][nb][3] * scale);
            if (!(vA && vc)) { e0 = 0.f; e1 = 0.f; }
            if (!(vB && vc)) { e2 = 0.f; e3 = 0.f; }
            rsum[mb * 2 + 0] += e0 + e1;
            rsum[mb * 2 + 1] += e2 + e3;
            csum0[nb] += e0 + e2;
            csum1[nb] += e1 + e3;
            if (vA && vc) {
                size_t off = ((size_t)b * LDIM + glA) * LDIM + gc;
                *(float2*)(econf + off) = make_float2(e0, e1);
                *(float2*)(mconf + off) = make_float2(0.f, 0.f);
            }
            if (vB && vc) {
                size_t off = ((size_t)b * LDIM + glB) * LDIM + gc;
                *(float2*)(econf + off) = make_float2(e2, e3);
                *(float2*)(mconf + off) = make_float2(0.f, 0.f);
            }
        }
    }

#pragma unroll
    for (int h = 0; h < 4; h++) {
        rsum[h] += __shfl_xor_sync(0xFFFFFFFFu, rsum[h], 1);
        rsum[h] += __shfl_xor_sync(0xFFFFFFFFu, rsum[h], 2);
    }
#pragma unroll
    for (int nb = 0; nb < 8; nb++) {
#pragma unroll
        for (int o = 4; o <= 16; o <<= 1) {
            csum0[nb] += __shfl_xor_sync(0xFFFFFFFFu, csum0[nb], o);
            csum1[nb] += __shfl_xor_sync(0xFFFFFFFFu, csum1[nb], o);
        }
    }

    float* rs = (float*)smc;
    float* cs = (float*)(smc + 1024);
    if ((lane & 3) == 0) {
#pragma unroll
        for (int h = 0; h < 4; h++) {
            int rl = wm * 32 + (h >> 1) * 16 + (h & 1) * 8 + (lane >> 2);
            rs[wn * 128 + rl] = rsum[h];
        }
    }
    if (lane < 4) {
#pragma unroll
        for (int nb = 0; nb < 8; nb++) {
            int cl = wn * 64 + nb * 8 + 2 * lane;
            cs[wm * 128 + cl]     = csum0[nb];
            cs[wm * 128 + cl + 1] = csum1[nb];
        }
    }
    __syncthreads();
    if (tid < 128) {
        float rv = rs[tid] + rs[128 + tid];
        if (l0 + tid < LDIM)
            g_rowpart[((size_t)b * LDIM + l0 + tid) * NT + nt] = rv;
        float cv = cs[tid] + cs[128 + tid] + cs[256 + tid] + cs[384 + tid];
        if (s0 + tid < LDIM)
            g_colpart[((size_t)b * NT + mt) * LDIM + s0 + tid] = cv;
    }
}

// ---------------- Pass 1b: fixed-order reduce; reset max keys ------------------
__global__ void k_reduce()
{
    int t = blockIdx.x * blockDim.x + threadIdx.x;
    const int n = BATCH * LDIM;
    if (t < n) {
        float s = 0.f;
#pragma unroll
        for (int i = 0; i < NT; i++) s += g_rowpart[(size_t)t * NT + i];
        g_invR[t]   = 1.f / s;
        g_rowmax[t] = 0ull;
    } else if (t < 2 * n) {
        int u = t - n;
        int b = u / LDIM, sidx = u % LDIM;
        float s = 0.f;
#pragma unroll
        for (int i = 0; i < NT; i++) s += g_colpart[((size_t)b * NT + i) * LDIM + sidx];
        g_invC[u]   = 1.f / s;
        g_colmax[u] = 0ull;
    }
}

// ---------------- Pass 2: conf = e^2*invR*invC; 64 rows/block ------------------
__global__ __launch_bounds__(256)
void k_conf(float* __restrict__ conf)
{
    const int b  = blockIdx.z;
    const int l0 = blockIdx.y * CROWS;
    const int s0 = blockIdx.x * CCOLS;
    const int t  = threadIdx.x, warp = t >> 5, lane = t & 31;
    const int j0 = s0 + 4 * t;
    const bool jok = j0 < LDIM;

    __shared__ float sInvR[CROWS];
    __shared__ unsigned long long wr[8][CROWS];

    if (t < CROWS) sInvR[t] = g_invR[b * LDIM + l0 + t];
    __syncthreads();

    const float4 invc = jok ? *(const float4*)(g_invC + b * LDIM + j0)
                            : make_float4(0.f, 0.f, 0.f, 0.f);

    float cv0 = -1.f, cv1 = -1.f, cv2 = -1.f, cv3 = -1.f;
    int   ci0 = 0, ci1 = 0, ci2 = 0, ci3 = 0;

    size_t base = ((size_t)b * LDIM + l0) * LDIM + (jok ? j0 : 0);

    for (int r = 0; r < CROWS; r++, base += LDIM) {
        unsigned long long rk = 0ull;
        if (jok) {
            float4 e = *(const float4*)(conf + base);
            const float tR = sInvR[r];
            float4 cf;
            cf.x = e.x * e.x * (tR * invc.x);
            cf.y = e.y * e.y * (tR * invc.y);
            cf.z = e.z * e.z * (tR * invc.z);
            cf.w = e.w * e.w * (tR * invc.w);
            *(float4*)(conf + base) = cf;

            if (cf.x > cv0) { cv0 = cf.x; ci0 = r; }
            if (cf.y > cv1) { cv1 = cf.y; ci1 = r; }
            if (cf.z > cv2) { cv2 = cf.z; ci2 = r; }
            if (cf.w > cv3) { cv3 = cf.w; ci3 = r; }

            float a = cf.x; int ia = 0;
            if (cf.y > a) { a = cf.y; ia = 1; }
            if (cf.z > a) { a = cf.z; ia = 2; }
            if (cf.w > a) { a = cf.w; ia = 3; }
            rk = ((unsigned long long)__float_as_uint(a) << 32)
               | (0xFFFFFFFFu ^ (unsigned)(j0 + ia));
        }
#pragma unroll
        for (int o = 16; o > 0; o >>= 1) {
            unsigned long long oth = __shfl_down_sync(0xFFFFFFFFu, rk, o);
            rk = (oth > rk) ? oth : rk;
        }
        if (lane == 0) wr[warp][r] = rk;
    }

    if (jok) {
        atomicMax(&g_colmax[b * LDIM + j0 + 0],
                  ((unsigned long long)__float_as_uint(cv0) << 32) | (0xFFFFFFFFu ^ (unsigned)(l0 + ci0)));
        atomicMax(&g_colmax[b * LDIM + j0 + 1],
                  ((unsigned long long)__float_as_uint(cv1) << 32) | (0xFFFFFFFFu ^ (unsigned)(l0 + ci1)));
        atomicMax(&g_colmax[b * LDIM + j0 + 2],
                  ((unsigned long long)__float_as_uint(cv2) << 32) | (0xFFFFFFFFu ^ (unsigned)(l0 + ci2)));
        atomicMax(&g_colmax[b * LDIM + j0 + 3],
                  ((unsigned long long)__float_as_uint(cv3) << 32) | (0xFFFFFFFFu ^ (unsigned)(l0 + ci3)));
    }
    __syncthreads();
    if (t < CROWS) {
        unsigned long long m = 0ull;
#pragma unroll
        for (int w = 0; w < 8; w++) m = (wr[w][t] > m) ? wr[w][t] : m;
        atomicMax(&g_rowmax[b * LDIM + l0 + t], m);
    }
}

// ---------------- Pass 3: mutual-NN + threshold + border -----------------------
__global__ void k_select(float* __restrict__ mconf)
{
    int t = blockIdx.x * blockDim.x + threadIdx.x;
    const int n = BATCH * LDIM;
    if (t >= 2 * n) return;
    const bool isrow = (t < n);
    const int  u = isrow ? t : (t - n);
    const int  b = u / LDIM;
    const int  p = u % LDIM;

    unsigned long long key = isrow ? g_rowmax[u] : g_colmax[u];
    float v = __uint_as_float((unsigned)(key >> 32));
    unsigned q = 0xFFFFFFFFu ^ (unsigned)key;
    if (!(v > THRV)) return;
    if (q >= (unsigned)LDIM) return;

    int l = isrow ? p : (int)q;
    int s = isrow ? (int)q : p;
    if (!border_ok(l) || !border_ok(s)) return;

    unsigned long long okey = isrow ? g_colmax[b * LDIM + s] : g_rowmax[b * LDIM + l];
    float ov = __uint_as_float((unsigned)(okey >> 32));
    if (ov == v)
        mconf[((size_t)b * LDIM + l) * LDIM + s] = v;
}

// ---------------- launch -------------------------------------------------------
extern "C" void kernel_launch(void* const* d_in, const int* in_sizes, int n_in,
                              void* d_out, int out_size)
{
    const float *f0 = nullptr, *f1 = nullptr, *temp = nullptr;
    for (int i = 0; i < n_in; i++) {
        if (in_sizes[i] == 1) { if (!temp) temp = (const float*)d_in[i]; }
        else { if (!f0) f0 = (const float*)d_in[i]; else if (!f1) f1 = (const float*)d_in[i]; }
    }

    float* conf  = (float*)d_out;
    float* mconf = conf + (size_t)out_size / 2;

    cudaFuncSetAttribute(k_gemm_hmma, cudaFuncAttributeMaxDynamicSharedMemorySize, SMEM_BYTES);

    const int NSPLIT = 2 * BATCH * LDIM * CDIM / 8;
    k_split<<<(NSPLIT + 255) / 256, 256>>>(f0, f1);

    dim3 g1(NT, NT, BATCH);
    k_gemm_hmma<<<g1, 256, SMEM_BYTES>>>(temp, conf, mconf);

    const int n2 = 2 * BATCH * LDIM;
    k_reduce<<<(n2 + 255) / 256, 256>>>();

    dim3 g2((LDIM + CCOLS - 1) / CCOLS, LDIM / CROWS, BATCH);
    k_conf<<<g2, 256>>>(conf);

    k_select<<<(n2 + 255) / 256, 256>>>(mconf);
}